// round 8
// baseline (speedup 1.0000x reference)
#include <cuda_runtime.h>
#include <cuda_fp16.h>
#include <cstdint>

#define N_PTS   10242
#define C_DIM   64
#define K_DIM   9
#define NBR_DIM 7
#define O_DIM   64
#define BT_DIM  16
#define M_TOTAL (BT_DIM * N_PTS)     /* 163872 */
#define HM      (M_TOTAL / 2)        /* 81936  */
#define CK_DIM  (C_DIM * K_DIM)      /* 576    */
#define X_ELEMS ((size_t)BT_DIM * N_PTS * C_DIM)   /* 10487808 */

#define BM       128
#define BK       32
#define N_CHUNKS (CK_DIM / BK)       /* 18 */
#define A_LDB    80

// ---------------- scratch ----------------------------------------------------
__device__ __half g_x16[X_ELEMS];                    // x in fp16 (21 MB)
__device__ __half g_A[(size_t)HM * CK_DIM];          // A half-size (94.4 MB)
__device__ uint4  g_Wfrag[2 * N_CHUNKS * 2 * 2 * 32];
__device__ int    g_any;

// ---------------- PTX helpers ------------------------------------------------
__device__ __forceinline__ uint32_t smem_u32(const void* p) {
    uint32_t a;
    asm("{ .reg .u64 t; cvta.to.shared.u64 t, %1; cvt.u32.u64 %0, t; }"
        : "=r"(a) : "l"(p));
    return a;
}

#define LDSM_X4(r, addr) \
    asm volatile("ldmatrix.sync.aligned.m8n8.x4.shared.b16 {%0,%1,%2,%3}, [%4];" \
        : "=r"((r)[0]), "=r"((r)[1]), "=r"((r)[2]), "=r"((r)[3]) : "r"(addr))

#define MMA_F16(d, a, b0, b1) \
    asm volatile("mma.sync.aligned.m16n8k16.row.col.f32.f16.f16.f32 " \
        "{%0,%1,%2,%3}, {%4,%5,%6,%7}, {%8,%9}, {%0,%1,%2,%3};" \
        : "+f"((d)[0]), "+f"((d)[1]), "+f"((d)[2]), "+f"((d)[3]) \
        : "r"((a)[0]), "r"((a)[1]), "r"((a)[2]), "r"((a)[3]), "r"(b0), "r"(b1))

// ---------------- setup kernels ----------------------------------------------
__global__ void prepack_wfrag_kernel(const float* __restrict__ conv_w) {
    if (blockIdx.x == 0 && threadIdx.x == 0) g_any = 0;
    int u = blockIdx.x * 256 + threadIdx.x;
    const int TOT = 2 * N_CHUNKS * 2 * 2 * 32 * 4;
    if (u >= TOT) return;
    int j    = u & 3;
    int lane = (u >> 2) & 31;
    int g    = (u >> 7) & 1;
    int ks   = (u >> 8) & 1;
    int ch   = (u >> 9) % N_CHUNKS;
    int wn   = u / (N_CHUNKS * 512);

    int o  = wn * 32 + g * 16 + (j >> 1) * 8 + (lane >> 2);
    int kg = ch * 32 + ks * 16 + (j & 1) * 8 + (lane & 3) * 2;

    float w0 = conv_w[(o * 64 + (kg & 63)) * 9 + (kg >> 6)];
    float w1 = conv_w[(o * 64 + ((kg + 1) & 63)) * 9 + ((kg + 1) >> 6)];
    __half h0 = __float2half_rn(w0);
    __half h1 = __float2half_rn(w1);
    uint32_t packed = ((uint32_t)*(uint16_t*)&h1 << 16) | *(uint16_t*)&h0;
    ((uint32_t*)g_Wfrag)[u] = packed;
}

__global__ void detect_idx_kernel(const int* __restrict__ idx32) {
    int any = 0;
    const int pairs = N_PTS * NBR_DIM / 2;
    for (int i = blockIdx.x * 256 + threadIdx.x; i < pairs; i += gridDim.x * 256)
        any |= (idx32[2 * i + 1] != 0);
    any = __syncthreads_or(any);
    if (threadIdx.x == 0 && any) atomicOr(&g_any, 1);
}

// x fp32 -> fp16 (4 elems/thread)
__global__ void cvt_x_kernel(const float* __restrict__ x) {
    size_t i = ((size_t)blockIdx.x * 256 + threadIdx.x) * 4;
    if (i >= X_ELEMS) return;
    float4 v = *(const float4*)(x + i);
    __half2 h0 = __floats2half2_rn(v.x, v.y);
    __half2 h1 = __floats2half2_rn(v.z, v.w);
    uint2 u;
    u.x = *(uint32_t*)&h0;
    u.y = *(uint32_t*)&h1;
    *(uint2*)(g_x16 + i) = u;
}

// ---------------- phase 1: interpolation (fp16 x) -> fp16 A ------------------
// Block: 256 thr = 8 rows x 32 lanes; lane handles channels 2L, 2L+1.
// Processes rows [m_base + blk*8, ...); writes A at half-local row index.
__global__ void interp_kernel(const void* __restrict__ index_raw,
                              const float* __restrict__ itp_mat,
                              int m_base) {
    __shared__ float sT[8][NBR_DIM * K_DIM];
    __shared__ int   sIdx[8][NBR_DIM];
    const int tid  = threadIdx.x;
    const int r0   = blockIdx.x * 8;          // half-local base row
    const int is64 = (g_any == 0);

    for (int i = tid; i < 8 * 63; i += 256) {
        int mi = i / 63, e = i - mi * 63;
        int n = (m_base + r0 + mi) % N_PTS;
        sT[mi][e] = itp_mat[n * 63 + e];
    }
    if (tid < 8 * NBR_DIM) {
        int mi = tid / NBR_DIM, j = tid - mi * NBR_DIM;
        int n = (m_base + r0 + mi) % N_PTS;
        int v;
        if (is64) v = (int)((const long long*)index_raw)[n * NBR_DIM + j];
        else      v = ((const int*)index_raw)[n * NBR_DIM + j];
        sIdx[mi][j] = v;
    }
    __syncthreads();

    const int lane = tid & 31;
    const int mloc = tid >> 5;
    const int c0   = lane * 2;
    const int m    = m_base + r0 + mloc;
    const int bt   = m / N_PTS;
    const __half* xb = g_x16 + (size_t)bt * N_PTS * C_DIM;

    float a0[K_DIM], a1[K_DIM];
#pragma unroll
    for (int k = 0; k < K_DIM; k++) { a0[k] = 0.f; a1[k] = 0.f; }

#pragma unroll
    for (int j = 0; j < NBR_DIM; j++) {
        uint32_t raw = *(const uint32_t*)(xb + (size_t)sIdx[mloc][j] * C_DIM + c0);
        float2 v = __half22float2(*(__half2*)&raw);
        const float* tj = &sT[mloc][j * K_DIM];
#pragma unroll
        for (int k = 0; k < K_DIM; k++) {
            a0[k] = fmaf(v.x, tj[k], a0[k]);
            a1[k] = fmaf(v.y, tj[k], a1[k]);
        }
    }

    __half* dst = g_A + (size_t)(r0 + mloc) * CK_DIM + c0;   // default policy: stay in L2
#pragma unroll
    for (int k = 0; k < K_DIM; k++) {
        __half2 h = __floats2half2_rn(a0[k], a1[k]);
        *(__half2*)(dst + k * 64) = h;
    }
}

// ---------------- phase 2: HMMA fp16 GEMM (A from L2, W frag-LDG) ------------
__global__ void __launch_bounds__(256, 2)
gemm_mma_kernel(const float* __restrict__ conv_b, float* __restrict__ out,
                int m_base) {
    __shared__ uint8_t sA[BM * A_LDB];

    const int tid = threadIdx.x;
    const int wid = tid >> 5;
    const int lid = tid & 31;
    const int wm  = wid & 3;
    const int wn  = wid >> 2;
    const int r0  = blockIdx.x * BM;          // half-local base row

    const uint32_t aFragOff =
        (uint32_t)((wm * 32 + ((lid >> 3) & 1) * 8 + (lid & 7)) * A_LDB
                   + (lid >> 4) * 16);
    const uint32_t uA = smem_u32(sA);

    float acc[2][4][4];
#pragma unroll
    for (int s = 0; s < 2; s++)
#pragma unroll
        for (int n = 0; n < 4; n++)
#pragma unroll
            for (int q = 0; q < 4; q++) acc[s][n][q] = 0.f;

    const int aRow0 = tid >> 2;
    const int aU    = tid & 3;
    const char* pA = (const char*)g_A;
    const uint4* pW = g_Wfrag + (size_t)(wn * N_CHUNKS) * 4 * 32 + lid;

    uint4 rA[2], wcur[4], wnxt[4];
    const uint4 Z4 = make_uint4(0, 0, 0, 0);

#pragma unroll
    for (int i = 0; i < 2; i++) {
        int r = r0 + aRow0 + i * 64;
        size_t off = (size_t)r * (CK_DIM * 2) + aU * 16;
        rA[i] = (r < HM) ? __ldcs((const uint4*)(pA + off)) : Z4;
    }
#pragma unroll
    for (int q = 0; q < 4; q++) wcur[q] = __ldg(pW + q * 32);

    for (int ch = 0; ch < N_CHUNKS; ch++) {
        __syncthreads();
#pragma unroll
        for (int i = 0; i < 2; i++)
            *(uint4*)(sA + (aRow0 + i * 64) * A_LDB + aU * 16) = rA[i];
        __syncthreads();

        if (ch + 1 < N_CHUNKS) {
            const int ccB = (ch + 1) * BK * 2;
#pragma unroll
            for (int i = 0; i < 2; i++) {
                int r = r0 + aRow0 + i * 64;
                size_t off = (size_t)r * (CK_DIM * 2) + ccB + aU * 16;
                rA[i] = (r < HM) ? __ldcs((const uint4*)(pA + off)) : Z4;
            }
#pragma unroll
            for (int q = 0; q < 4; q++)
                wnxt[q] = __ldg(pW + ((ch + 1) * 4 + q) * 32);
        }

#pragma unroll
        for (int ks = 0; ks < 2; ks++) {
            const uint32_t kB = ks * 32;
            uint32_t af[2][4];
#pragma unroll
            for (int s = 0; s < 2; s++)
                LDSM_X4(af[s], uA + aFragOff + s * 16 * A_LDB + kB);
#pragma unroll
            for (int s = 0; s < 2; s++)
#pragma unroll
                for (int g = 0; g < 2; g++) {
                    const uint4 w = wcur[ks * 2 + g];
                    MMA_F16(acc[s][g * 2 + 0], af[s], w.x, w.y);
                    MMA_F16(acc[s][g * 2 + 1], af[s], w.z, w.w);
                }
        }
#pragma unroll
        for (int q = 0; q < 4; q++) wcur[q] = wnxt[q];
    }

    // ---- epilogue ----
    float bias[4][2];
#pragma unroll
    for (int n = 0; n < 4; n++) {
        int ob = wn * 32 + n * 8 + (lid & 3) * 2;
        bias[n][0] = __ldg(conv_b + ob);
        bias[n][1] = __ldg(conv_b + ob + 1);
    }
#pragma unroll
    for (int s = 0; s < 2; s++)
#pragma unroll
        for (int h = 0; h < 2; h++) {
            int r = r0 + wm * 32 + s * 16 + h * 8 + (lid >> 2);
            if (r < HM) {
                float* op = out + (size_t)(m_base + r) * O_DIM
                              + wn * 32 + (lid & 3) * 2;
#pragma unroll
                for (int n = 0; n < 4; n++) {
                    float2 v;
                    v.x = acc[s][n][h * 2 + 0] + bias[n][0];
                    v.y = acc[s][n][h * 2 + 1] + bias[n][1];
                    *(float2*)(op + n * 8) = v;
                }
            }
        }
}

// ---------------------------------------------------------------------------
extern "C" void kernel_launch(void* const* d_in, const int* in_sizes, int n_in,
                              void* d_out, int out_size) {
    const float* x       = (const float*)d_in[0];
    const void*  index   = d_in[1];
    const float* itp_mat = (const float*)d_in[2];
    const float* conv_w  = (const float*)d_in[3];
    const float* conv_b  = (const float*)d_in[4];
    float*       out     = (float*)d_out;

    prepack_wfrag_kernel<<<144, 256>>>(conv_w);
    detect_idx_kernel<<<64, 256>>>((const int*)index);
    cvt_x_kernel<<<(int)((X_ELEMS / 4 + 255) / 256), 256>>>(x);

    const int gemm_grid   = (HM + BM - 1) / BM;   // 641
    const int interp_grid = HM / 8;               // 10242
    for (int h = 0; h < 2; h++) {
        interp_kernel<<<interp_grid, 256>>>(index, itp_mat, h * HM);
        gemm_mma_kernel<<<gemm_grid, 256>>>(conv_b, out, h * HM);
    }
}

// round 9
// speedup vs baseline: 1.6401x; 1.6401x over previous
#include <cuda_runtime.h>
#include <cuda_fp16.h>
#include <cstdint>

#define N_PTS   10242
#define C_DIM   64
#define K_DIM   9
#define NBR_DIM 7
#define O_DIM   64
#define BT_DIM  16
#define M_TOTAL (BT_DIM * N_PTS)     /* 163872 */
#define CK_DIM  (C_DIM * K_DIM)      /* 576    */

#define BM       128
#define BK       32
#define N_CHUNKS (CK_DIM / BK)       /* 18 */
#define A_LDB    80                  /* smem row pitch bytes: 64 B + 16 pad */

// ---------------- scratch ----------------------------------------------------
__device__ __half g_A[(size_t)M_TOTAL * CK_DIM];     // A fp16, [m][k*64+c]
// W in MMA B-fragment layout: [wn][ch][ks][g] -> 32 lanes x uint4
__device__ uint4  g_Wfrag[2 * N_CHUNKS * 2 * 2 * 32];
__device__ int    g_any;

// ---------------- PTX helpers ------------------------------------------------
__device__ __forceinline__ uint32_t smem_u32(const void* p) {
    uint32_t a;
    asm("{ .reg .u64 t; cvta.to.shared.u64 t, %1; cvt.u32.u64 %0, t; }"
        : "=r"(a) : "l"(p));
    return a;
}

#define LDSM_X4(r, addr) \
    asm volatile("ldmatrix.sync.aligned.m8n8.x4.shared.b16 {%0,%1,%2,%3}, [%4];" \
        : "=r"((r)[0]), "=r"((r)[1]), "=r"((r)[2]), "=r"((r)[3]) : "r"(addr))

#define MMA_F16(d, a, b0, b1) \
    asm volatile("mma.sync.aligned.m16n8k16.row.col.f32.f16.f16.f32 " \
        "{%0,%1,%2,%3}, {%4,%5,%6,%7}, {%8,%9}, {%0,%1,%2,%3};" \
        : "+f"((d)[0]), "+f"((d)[1]), "+f"((d)[2]), "+f"((d)[3]) \
        : "r"((a)[0]), "r"((a)[1]), "r"((a)[2]), "r"((a)[3]), "r"(b0), "r"(b1))

// ---------------- setup kernels ----------------------------------------------
__global__ void prepack_wfrag_kernel(const float* __restrict__ conv_w) {
    if (blockIdx.x == 0 && threadIdx.x == 0) g_any = 0;
    int u = blockIdx.x * 256 + threadIdx.x;
    const int TOT = 2 * N_CHUNKS * 2 * 2 * 32 * 4;
    if (u >= TOT) return;
    int j    = u & 3;
    int lane = (u >> 2) & 31;
    int g    = (u >> 7) & 1;
    int ks   = (u >> 8) & 1;
    int ch   = (u >> 9) % N_CHUNKS;
    int wn   = u / (N_CHUNKS * 512);

    int o  = wn * 32 + g * 16 + (j >> 1) * 8 + (lane >> 2);
    int kg = ch * 32 + ks * 16 + (j & 1) * 8 + (lane & 3) * 2;

    float w0 = conv_w[(o * 64 + (kg & 63)) * 9 + (kg >> 6)];
    float w1 = conv_w[(o * 64 + ((kg + 1) & 63)) * 9 + ((kg + 1) >> 6)];
    __half h0 = __float2half_rn(w0);
    __half h1 = __float2half_rn(w1);
    uint32_t packed = ((uint32_t)*(uint16_t*)&h1 << 16) | *(uint16_t*)&h0;
    ((uint32_t*)g_Wfrag)[u] = packed;
}

__global__ void detect_idx_kernel(const int* __restrict__ idx32) {
    int any = 0;
    const int pairs = N_PTS * NBR_DIM / 2;
    for (int i = blockIdx.x * 256 + threadIdx.x; i < pairs; i += gridDim.x * 256)
        any |= (idx32[2 * i + 1] != 0);
    any = __syncthreads_or(any);
    if (threadIdx.x == 0 && any) atomicOr(&g_any, 1);
}

// ---------------- phase 1: interpolation -> fp16 A ---------------------------
// Block: 256 thr = 16 rows x 16 lanes; lane handles channels 4L..4L+3.
// float4 gathers (256 B per row-neighbor across 16 lanes).
__global__ void interp_kernel(const float* __restrict__ x,
                              const void*  __restrict__ index_raw,
                              const float* __restrict__ itp_mat) {
    __shared__ float sT[16][NBR_DIM * K_DIM];
    __shared__ int   sIdx[16][NBR_DIM];
    const int tid = threadIdx.x;
    const int m0  = blockIdx.x * 16;
    const int is64 = (g_any == 0);

    for (int i = tid; i < 16 * 63; i += 256) {
        int mi = i / 63, e = i - mi * 63;
        int n = (m0 + mi) % N_PTS;
        sT[mi][e] = itp_mat[n * 63 + e];
    }
    if (tid < 16 * NBR_DIM) {
        int mi = tid / NBR_DIM, j = tid - mi * NBR_DIM;
        int n = (m0 + mi) % N_PTS;
        int v;
        if (is64) v = (int)((const long long*)index_raw)[n * NBR_DIM + j];
        else      v = ((const int*)index_raw)[n * NBR_DIM + j];
        sIdx[mi][j] = v;
    }
    __syncthreads();

    const int lane = tid & 15;
    const int row  = tid >> 4;
    const int c0   = lane * 4;
    const int m    = m0 + row;                 // grid exact
    const int bt   = m / N_PTS;
    const float* xb = x + (size_t)bt * N_PTS * C_DIM + c0;

    float acc[K_DIM][4];
#pragma unroll
    for (int k = 0; k < K_DIM; k++)
#pragma unroll
        for (int q = 0; q < 4; q++) acc[k][q] = 0.f;

#pragma unroll
    for (int j = 0; j < NBR_DIM; j++) {
        float4 v = *(const float4*)(xb + (size_t)sIdx[row][j] * C_DIM);
        const float* tj = &sT[row][j * K_DIM];
#pragma unroll
        for (int k = 0; k < K_DIM; k++) {
            float t = tj[k];
            acc[k][0] = fmaf(v.x, t, acc[k][0]);
            acc[k][1] = fmaf(v.y, t, acc[k][1]);
            acc[k][2] = fmaf(v.z, t, acc[k][2]);
            acc[k][3] = fmaf(v.w, t, acc[k][3]);
        }
    }

    __half* dst = g_A + (size_t)m * CK_DIM + c0;
#pragma unroll
    for (int k = 0; k < K_DIM; k++) {
        __half2 h0 = __floats2half2_rn(acc[k][0], acc[k][1]);
        __half2 h1 = __floats2half2_rn(acc[k][2], acc[k][3]);
        uint2 u;
        u.x = *(uint32_t*)&h0;
        u.y = *(uint32_t*)&h1;
        __stcs((uint2*)(dst + k * 64), u);     // streaming store
    }
}

// ---------------- phase 2: HMMA fp16 GEMM (A smem, W frag-LDG) ---------------
__global__ void __launch_bounds__(256, 2)
gemm_mma_kernel(const float* __restrict__ conv_b, float* __restrict__ out) {
    __shared__ uint8_t sA[BM * A_LDB];          // 10 KB

    const int tid = threadIdx.x;
    const int wid = tid >> 5;
    const int lid = tid & 31;
    const int wm  = wid & 3;
    const int wn  = wid >> 2;
    const int m0  = blockIdx.x * BM;

    const uint32_t aFragOff =
        (uint32_t)((wm * 32 + ((lid >> 3) & 1) * 8 + (lid & 7)) * A_LDB
                   + (lid >> 4) * 16);
    const uint32_t uA = smem_u32(sA);

    float acc[2][4][4];
#pragma unroll
    for (int s = 0; s < 2; s++)
#pragma unroll
        for (int n = 0; n < 4; n++)
#pragma unroll
            for (int q = 0; q < 4; q++) acc[s][n][q] = 0.f;

    const int aRow0 = tid >> 2;
    const int aU    = tid & 3;
    const char* pA = (const char*)g_A;
    const uint4* pW = g_Wfrag + (size_t)(wn * N_CHUNKS) * 4 * 32 + lid;

    uint4 rA[2], wcur[4], wnxt[4];
    const uint4 Z4 = make_uint4(0, 0, 0, 0);

#pragma unroll
    for (int i = 0; i < 2; i++) {
        int m = m0 + aRow0 + i * 64;
        size_t off = (size_t)m * (CK_DIM * 2) + aU * 16;
        rA[i] = (m < M_TOTAL) ? __ldcs((const uint4*)(pA + off)) : Z4;
    }
#pragma unroll
    for (int q = 0; q < 4; q++) wcur[q] = __ldg(pW + q * 32);

    for (int ch = 0; ch < N_CHUNKS; ch++) {
        __syncthreads();
#pragma unroll
        for (int i = 0; i < 2; i++)
            *(uint4*)(sA + (aRow0 + i * 64) * A_LDB + aU * 16) = rA[i];
        __syncthreads();

        if (ch + 1 < N_CHUNKS) {
            const int ccB = (ch + 1) * BK * 2;
#pragma unroll
            for (int i = 0; i < 2; i++) {
                int m = m0 + aRow0 + i * 64;
                size_t off = (size_t)m * (CK_DIM * 2) + ccB + aU * 16;
                rA[i] = (m < M_TOTAL) ? __ldcs((const uint4*)(pA + off)) : Z4;
            }
#pragma unroll
            for (int q = 0; q < 4; q++)
                wnxt[q] = __ldg(pW + ((ch + 1) * 4 + q) * 32);
        }

#pragma unroll
        for (int ks = 0; ks < 2; ks++) {
            const uint32_t kB = ks * 32;
            uint32_t af[2][4];
#pragma unroll
            for (int s = 0; s < 2; s++)
                LDSM_X4(af[s], uA + aFragOff + s * 16 * A_LDB + kB);
#pragma unroll
            for (int s = 0; s < 2; s++)
#pragma unroll
                for (int g = 0; g < 2; g++) {
                    const uint4 w = wcur[ks * 2 + g];
                    MMA_F16(acc[s][g * 2 + 0], af[s], w.x, w.y);
                    MMA_F16(acc[s][g * 2 + 1], af[s], w.z, w.w);
                }
        }
#pragma unroll
        for (int q = 0; q < 4; q++) wcur[q] = wnxt[q];
    }

    // ---- epilogue ----
    float bias[4][2];
#pragma unroll
    for (int n = 0; n < 4; n++) {
        int ob = wn * 32 + n * 8 + (lid & 3) * 2;
        bias[n][0] = __ldg(conv_b + ob);
        bias[n][1] = __ldg(conv_b + ob + 1);
    }
#pragma unroll
    for (int s = 0; s < 2; s++)
#pragma unroll
        for (int h = 0; h < 2; h++) {
            int m = m0 + wm * 32 + s * 16 + h * 8 + (lid >> 2);
            if (m < M_TOTAL) {
                float* op = out + (size_t)m * O_DIM + wn * 32 + (lid & 3) * 2;
#pragma unroll
                for (int n = 0; n < 4; n++) {
                    float2 v;
                    v.x = acc[s][n][h * 2 + 0] + bias[n][0];
                    v.y = acc[s][n][h * 2 + 1] + bias[n][1];
                    *(float2*)(op + n * 8) = v;
                }
            }
        }
}

// ---------------------------------------------------------------------------
extern "C" void kernel_launch(void* const* d_in, const int* in_sizes, int n_in,
                              void* d_out, int out_size) {
    const float* x       = (const float*)d_in[0];
    const void*  index   = d_in[1];
    const float* itp_mat = (const float*)d_in[2];
    const float* conv_w  = (const float*)d_in[3];
    const float* conv_b  = (const float*)d_in[4];
    float*       out     = (float*)d_out;

    prepack_wfrag_kernel<<<144, 256>>>(conv_w);
    detect_idx_kernel<<<64, 256>>>((const int*)index);
    interp_kernel<<<M_TOTAL / 16, 256>>>(x, index, itp_mat);
    gemm_mma_kernel<<<(M_TOTAL + BM - 1) / BM, 256>>>(conv_b, out);
}